// round 6
// baseline (speedup 1.0000x reference)
#include <cuda_runtime.h>
#include <cstdint>

#define B_ 8
#define L_ 256
#define D_ 256
#define CH 32

// 64 MB scratch for h = relu(z @ W1 + b1) * mask   [B][L][L][CH]
__device__ float g_h[(size_t)B_ * L_ * L_ * CH];

// ---------- packed f32x2 helpers (sm_103a) ----------
__device__ __forceinline__ unsigned long long ffma2(unsigned long long a,
                                                    unsigned long long b,
                                                    unsigned long long c) {
    unsigned long long d;
    asm("fma.rn.f32x2 %0, %1, %2, %3;" : "=l"(d) : "l"(a), "l"(b), "l"(c));
    return d;
}
__device__ __forceinline__ unsigned long long dup2(float x) {
    unsigned long long d;
    asm("mov.b64 %0, {%1, %1};" : "=l"(d) : "f"(x));
    return d;
}
__device__ __forceinline__ float2 unpk(unsigned long long v) {
    float2 r;
    asm("mov.b64 {%0, %1}, %2;" : "=f"(r.x), "=f"(r.y) : "l"(v));
    return r;
}

// ============================================================
// Stage 1: h[b,i,j,c] = relu( sum_d x[b,i,d]x[b,j,d] W1[d,c]
//                           + sum_d |x[b,i,d]-x[b,j,d]| W1[256+d,c] + b1[c] ) * m
// 16x16 pair tile per CTA, 1 pair per thread, 32 channels packed as 16 f32x2.
// ============================================================
__global__ __launch_bounds__(256, 2)
void stage1_kernel(const float* __restrict__ x, const int* __restrict__ plen_g,
                   const float* __restrict__ W1, const float* __restrict__ b1) {
    extern __shared__ float smem[];
    float* sW1 = smem;                    // 512*32 = 16384 floats (64 KB)
    float* sxi = smem + 16384;            // 16 rows * 257 (padded)
    float* sxj = sxi + 16 * 257;

    const int b  = blockIdx.z;
    const int i0 = blockIdx.y * 16;
    const int j0 = blockIdx.x * 16;
    const int tid = threadIdx.x;
    const int ti = tid >> 4, tj = tid & 15;
    const int plen = plen_g[b];

    const int gi = i0 + ti, gj = j0 + tj;
    const size_t pix = (size_t)(b * L_ + gi) * L_ + gj;
    float4* outp = reinterpret_cast<float4*>(g_h + pix * CH);

    // fully masked tile: write zeros and bail (saves ~44% of compute on average)
    if (i0 >= plen || j0 >= plen) {
        float4 z = make_float4(0.f, 0.f, 0.f, 0.f);
        #pragma unroll
        for (int k = 0; k < 8; k++) outp[k] = z;
        return;
    }

    // fill W1 into shared (coalesced float4)
    {
        const float4* w4 = reinterpret_cast<const float4*>(W1);
        float4* s4 = reinterpret_cast<float4*>(sW1);
        #pragma unroll
        for (int k = 0; k < 16; k++) s4[tid + k * 256] = w4[tid + k * 256];
    }
    // fill x row tiles (padded stride 257 -> conflict-free strided reads)
    {
        const float* xb = x + (size_t)b * L_ * D_;
        #pragma unroll
        for (int k = 0; k < 16; k++) {
            int idx = tid + k * 256;
            int r = idx >> 8, c = idx & 255;
            sxi[r * 257 + c] = xb[(i0 + r) * D_ + c];
            sxj[r * 257 + c] = xb[(j0 + r) * D_ + c];
        }
    }
    __syncthreads();

    const bool valid = (gi < plen) && (gj < plen);

    unsigned long long acc[16];
    #pragma unroll
    for (int k = 0; k < 16; k++) acc[k] = 0ULL;   // packed {0.0f, 0.0f}

    if (valid) {
        const float* xi = sxi + ti * 257;
        const float* xj = sxj + tj * 257;
        #pragma unroll 2
        for (int d = 0; d < 256; d++) {
            float a = xi[d], bb = xj[d];
            unsigned long long p2 = dup2(a * bb);
            unsigned long long s2 = dup2(fabsf(a - bb));
            const ulonglong2* wa = reinterpret_cast<const ulonglong2*>(sW1 + d * 32);
            const ulonglong2* wb = reinterpret_cast<const ulonglong2*>(sW1 + (256 + d) * 32);
            #pragma unroll
            for (int k = 0; k < 8; k++) {
                ulonglong2 A  = wa[k];   // LDS.128: 2 packed f32x2 (uniform broadcast)
                ulonglong2 Bv = wb[k];
                acc[2 * k]     = ffma2(p2, A.x,  acc[2 * k]);
                acc[2 * k + 1] = ffma2(p2, A.y,  acc[2 * k + 1]);
                acc[2 * k]     = ffma2(s2, Bv.x, acc[2 * k]);
                acc[2 * k + 1] = ffma2(s2, Bv.y, acc[2 * k + 1]);
            }
        }
    }

    #pragma unroll
    for (int k = 0; k < 8; k++) {
        float2 lo = unpk(acc[2 * k]);
        float2 hi = unpk(acc[2 * k + 1]);
        float4 o;
        if (valid) {
            o.x = fmaxf(lo.x + b1[4 * k + 0], 0.f);
            o.y = fmaxf(lo.y + b1[4 * k + 1], 0.f);
            o.z = fmaxf(hi.x + b1[4 * k + 2], 0.f);
            o.w = fmaxf(hi.y + b1[4 * k + 3], 0.f);
        } else {
            o = make_float4(0.f, 0.f, 0.f, 0.f);
        }
        outp[k] = o;
    }
}

// ============================================================
// Stage 2: out[b,i,j] = ( sum_{di,dj,c} h[b,i+di-3,j+dj-3,c] * W2[di,dj,c] + b2 ) * m
// 32x32 output tile, 128 threads, 1x8 outputs/thread, sliding-window register row.
// Channels chunked by 8 in SMEM.
// ============================================================
#define SH_W 44                   // padded col stride (16B-aligned, bank-spread)
#define SH_PLANE (38 * SH_W)      // one channel plane: 38 rows

__global__ __launch_bounds__(128)
void stage2_kernel(const int* __restrict__ plen_g, const float* __restrict__ W2,
                   const float* __restrict__ b2, float* __restrict__ out) {
    extern __shared__ float smem[];
    float* sw = smem;             // 1568 weights, padded to 1600
    float* sh = smem + 1600;      // 8 channel planes

    const int b  = blockIdx.z;
    const int i0 = blockIdx.y * 32;
    const int j0 = blockIdx.x * 32;
    const int tid = threadIdx.x;
    const int row = tid >> 2;             // 0..31
    const int jc  = (tid & 3) * 8;        // 0,8,16,24
    const int plen = plen_g[b];
    const int i = i0 + row;

    float* outrow = out + ((size_t)(b * L_ + i) * L_ + j0 + jc);

    if (i0 >= plen || j0 >= plen) {       // fully masked tile
        #pragma unroll
        for (int q = 0; q < 8; q++) outrow[q] = 0.f;
        return;
    }

    for (int idx = tid; idx < 1568; idx += 128) sw[idx] = W2[idx];

    float acc[8];
    #pragma unroll
    for (int q = 0; q < 8; q++) acc[q] = 0.f;

    for (int cb = 0; cb < 4; cb++) {
        const int cbase = cb * 8;
        __syncthreads();   // sw ready (cb=0) / previous compute done (cb>0)
        // fill 38x38 halo tile, 8 channels per pixel (one 32B sector)
        for (int p = tid; p < 38 * 38; p += 128) {
            int rr = p / 38, cc = p - rr * 38;
            int rg = i0 - 3 + rr, cg = j0 - 3 + cc;
            float4 v0 = make_float4(0.f, 0.f, 0.f, 0.f);
            float4 v1 = v0;
            if (rg >= 0 && rg < L_ && cg >= 0 && cg < L_) {
                const float4* hp = reinterpret_cast<const float4*>(
                    g_h + ((size_t)(b * L_ + rg) * L_ + cg) * CH + cbase);
                v0 = hp[0];
                v1 = hp[1];
            }
            float* d0 = sh + rr * SH_W + cc;
            d0[0 * SH_PLANE] = v0.x; d0[1 * SH_PLANE] = v0.y;
            d0[2 * SH_PLANE] = v0.z; d0[3 * SH_PLANE] = v0.w;
            d0[4 * SH_PLANE] = v1.x; d0[5 * SH_PLANE] = v1.y;
            d0[6 * SH_PLANE] = v1.z; d0[7 * SH_PLANE] = v1.w;
        }
        __syncthreads();

        #pragma unroll
        for (int ch = 0; ch < 8; ch++) {
            #pragma unroll
            for (int di = 0; di < 7; di++) {
                const float4* hp = reinterpret_cast<const float4*>(
                    sh + ch * SH_PLANE + (row + di) * SH_W + jc);
                float4 h0 = hp[0], h1 = hp[1], h2 = hp[2], h3 = hp[3];
                float hr[16] = {h0.x, h0.y, h0.z, h0.w, h1.x, h1.y, h1.z, h1.w,
                                h2.x, h2.y, h2.z, h2.w, h3.x, h3.y, h3.z, h3.w};
                const float* wr = sw + di * 7 * 32 + cbase + ch;
                #pragma unroll
                for (int dj = 0; dj < 7; dj++) {
                    float w = wr[dj * 32];    // warp-uniform broadcast
                    #pragma unroll
                    for (int q = 0; q < 8; q++)
                        acc[q] = fmaf(hr[q + dj], w, acc[q]);
                }
            }
        }
    }

    const float bias = b2[0];
    #pragma unroll
    for (int q = 0; q < 8; q++) {
        int j = j0 + jc + q;
        outrow[q] = (i < plen && j < plen) ? (acc[q] + bias) : 0.f;
    }
}

// ============================================================
extern "C" void kernel_launch(void* const* d_in, const int* in_sizes, int n_in,
                              void* d_out, int out_size) {
    const float* x  = (const float*)d_in[0];   // [8,256,256] f32
    const int*   pl = (const int*)  d_in[1];   // [8] i32
    const float* W1 = (const float*)d_in[2];   // [512,32] f32
    const float* b1 = (const float*)d_in[3];   // [32] f32
    const float* W2 = (const float*)d_in[4];   // [7,7,32,1] f32
    const float* b2 = (const float*)d_in[5];   // [1] f32
    float* out = (float*)d_out;                // [8,256,256,1] f32

    const int smem1 = (16384 + 2 * 16 * 257) * 4;          // 98432 B
    const int smem2 = (1600 + 8 * SH_PLANE) * 4;           // 59904 B
    cudaFuncSetAttribute(stage1_kernel, cudaFuncAttributeMaxDynamicSharedMemorySize, smem1);
    cudaFuncSetAttribute(stage2_kernel, cudaFuncAttributeMaxDynamicSharedMemorySize, smem2);

    dim3 g1(16, 16, 8);
    stage1_kernel<<<g1, 256, smem1>>>(x, pl, W1, b1);
    dim3 g2(8, 8, 8);
    stage2_kernel<<<g2, 128, smem2>>>(pl, W2, b2, out);
}

// round 7
// speedup vs baseline: 1.1181x; 1.1181x over previous
#include <cuda_runtime.h>
#include <cstdint>

#define B_ 8
#define L_ 256
#define D_ 256
#define CH 32

// 64 MB scratch for h = relu(z @ W1 + b1) * mask   [B][L][L][CH]
__device__ float g_h[(size_t)B_ * L_ * L_ * CH];

// ---------- packed f32x2 helpers (sm_103a) ----------
__device__ __forceinline__ unsigned long long ffma2(unsigned long long a,
                                                    unsigned long long b,
                                                    unsigned long long c) {
    unsigned long long d;
    asm("fma.rn.f32x2 %0, %1, %2, %3;" : "=l"(d) : "l"(a), "l"(b), "l"(c));
    return d;
}
__device__ __forceinline__ unsigned long long dup2(float x) {
    unsigned long long d;
    asm("mov.b64 %0, {%1, %1};" : "=l"(d) : "f"(x));
    return d;
}
__device__ __forceinline__ float2 unpk(unsigned long long v) {
    float2 r;
    asm("mov.b64 {%0, %1}, %2;" : "=f"(r.x), "=f"(r.y) : "l"(v));
    return r;
}

// ============================================================
// Stage 1: h[b,i,j,c] = relu( sum_d x[b,i,d]x[b,j,d] W1[d,c]
//                           + sum_d |x[b,i,d]-x[b,j,d]| W1[256+d,c] + b1[c] ) * m
// 16(i) x 32(j) tile, 128 threads, each thread 4 pairs (2i x 2j),
// 32 channels packed as 16 f32x2 per pair -> 64 u64 accumulators.
// W1 staged in 2 K-halves (32 KB each) so 2 CTAs/SM fit.
// ============================================================
__global__ __launch_bounds__(128, 2)
void stage1_kernel(const float* __restrict__ x, const int* __restrict__ plen_g,
                   const float* __restrict__ W1, const float* __restrict__ b1) {
    extern __shared__ float smem[];
    float* sWm = smem;                 // 128 x 32 (mul weights, current half)
    float* sWs = smem + 4096;          // 128 x 32 (sub weights, current half)
    float* sxi = smem + 8192;          // 16 rows * 257
    float* sxj = sxi + 16 * 257;       // 32 rows * 257

    const int b  = blockIdx.z;
    const int i0 = blockIdx.y * 16;
    const int j0 = blockIdx.x * 32;
    const int tid = threadIdx.x;
    const int ti = tid >> 4;           // 0..7
    const int tj = tid & 15;           // 0..15
    const int plen = plen_g[b];

    const int gi0 = i0 + ti, gi1 = i0 + ti + 8;
    const int gj0 = j0 + tj, gj1 = j0 + tj + 16;

    float* h_base = g_h + (size_t)b * L_ * L_ * CH;
    const int gis[2] = {gi0, gi1};
    const int gjs[2] = {gj0, gj1};

    if (i0 >= plen || j0 >= plen) {    // fully masked tile: zero-fill, bail
        float4 z = make_float4(0.f, 0.f, 0.f, 0.f);
        #pragma unroll
        for (int pi = 0; pi < 2; pi++)
            #pragma unroll
            for (int pj = 0; pj < 2; pj++) {
                float4* op = reinterpret_cast<float4*>(
                    h_base + ((size_t)gis[pi] * L_ + gjs[pj]) * CH);
                #pragma unroll
                for (int k = 0; k < 8; k++) op[k] = z;
            }
        return;
    }

    // stage x tiles (float4 global loads, scalar smem stores; stride 257)
    {
        const float* xb = x + (size_t)b * L_ * D_;
        const float4* xb4 = reinterpret_cast<const float4*>(xb);
        #pragma unroll
        for (int it = 0; it < 8; it++) {           // 16*64 float4
            int idx = tid + it * 128;
            int r = idx >> 6, c = (idx & 63) * 4;
            float4 v = xb4[(i0 + r) * 64 + (c >> 2)];
            float* d0 = sxi + r * 257 + c;
            d0[0] = v.x; d0[1] = v.y; d0[2] = v.z; d0[3] = v.w;
        }
        #pragma unroll
        for (int it = 0; it < 16; it++) {          // 32*64 float4
            int idx = tid + it * 128;
            int r = idx >> 6, c = (idx & 63) * 4;
            float4 v = xb4[(j0 + r) * 64 + (c >> 2)];
            float* d0 = sxj + r * 257 + c;
            d0[0] = v.x; d0[1] = v.y; d0[2] = v.z; d0[3] = v.w;
        }
    }

    unsigned long long acc[4][16];
    #pragma unroll
    for (int p = 0; p < 4; p++)
        #pragma unroll
        for (int k = 0; k < 16; k++) acc[p][k] = 0ULL;

    const float* xi0 = sxi + ti * 257;
    const float* xi1 = sxi + (ti + 8) * 257;
    const float* xj0 = sxj + tj * 257;
    const float* xj1 = sxj + (tj + 16) * 257;

    for (int half = 0; half < 2; half++) {
        if (half) __syncthreads();     // everyone done reading previous sW
        // load this K-half of W1: mul rows [half*128, +128), sub rows [256+half*128, +128)
        {
            const float4* wm4 = reinterpret_cast<const float4*>(W1 + half * 128 * 32);
            const float4* ws4 = reinterpret_cast<const float4*>(W1 + (256 + half * 128) * 32);
            float4* sm4 = reinterpret_cast<float4*>(sWm);
            float4* ss4 = reinterpret_cast<float4*>(sWs);
            #pragma unroll
            for (int k = 0; k < 8; k++) {
                sm4[tid + k * 128] = wm4[tid + k * 128];
                ss4[tid + k * 128] = ws4[tid + k * 128];
            }
        }
        __syncthreads();               // sW ready (and x tiles ready on half 0)

        const int dof = half * 128;
        #pragma unroll 2
        for (int dd = 0; dd < 128; dd++) {
            float a0 = xi0[dof + dd], a1 = xi1[dof + dd];
            float c0 = xj0[dof + dd], c1 = xj1[dof + dd];
            unsigned long long p00 = dup2(a0 * c0);
            unsigned long long p01 = dup2(a0 * c1);
            unsigned long long p10 = dup2(a1 * c0);
            unsigned long long p11 = dup2(a1 * c1);
            unsigned long long s00 = dup2(fabsf(a0 - c0));
            unsigned long long s01 = dup2(fabsf(a0 - c1));
            unsigned long long s10 = dup2(fabsf(a1 - c0));
            unsigned long long s11 = dup2(fabsf(a1 - c1));
            const ulonglong2* wm = reinterpret_cast<const ulonglong2*>(sWm + dd * 32);
            const ulonglong2* ws = reinterpret_cast<const ulonglong2*>(sWs + dd * 32);
            #pragma unroll
            for (int k = 0; k < 8; k++) {
                ulonglong2 M = wm[k];      // LDS.128, warp-uniform broadcast
                ulonglong2 S = ws[k];
                acc[0][2*k]   = ffma2(p00, M.x, acc[0][2*k]);
                acc[0][2*k+1] = ffma2(p00, M.y, acc[0][2*k+1]);
                acc[1][2*k]   = ffma2(p01, M.x, acc[1][2*k]);
                acc[1][2*k+1] = ffma2(p01, M.y, acc[1][2*k+1]);
                acc[2][2*k]   = ffma2(p10, M.x, acc[2][2*k]);
                acc[2][2*k+1] = ffma2(p10, M.y, acc[2][2*k+1]);
                acc[3][2*k]   = ffma2(p11, M.x, acc[3][2*k]);
                acc[3][2*k+1] = ffma2(p11, M.y, acc[3][2*k+1]);
                acc[0][2*k]   = ffma2(s00, S.x, acc[0][2*k]);
                acc[0][2*k+1] = ffma2(s00, S.y, acc[0][2*k+1]);
                acc[1][2*k]   = ffma2(s01, S.x, acc[1][2*k]);
                acc[1][2*k+1] = ffma2(s01, S.y, acc[1][2*k+1]);
                acc[2][2*k]   = ffma2(s10, S.x, acc[2][2*k]);
                acc[2][2*k+1] = ffma2(s10, S.y, acc[2][2*k+1]);
                acc[3][2*k]   = ffma2(s11, S.x, acc[3][2*k]);
                acc[3][2*k+1] = ffma2(s11, S.y, acc[3][2*k+1]);
            }
        }
    }

    // epilogue: bias + relu + mask, 4 pairs
    const float4* b4 = reinterpret_cast<const float4*>(b1);
    #pragma unroll
    for (int pi = 0; pi < 2; pi++) {
        #pragma unroll
        for (int pj = 0; pj < 2; pj++) {
            const int p = pi * 2 + pj;
            const bool valid = (gis[pi] < plen) && (gjs[pj] < plen);
            float4* op = reinterpret_cast<float4*>(
                h_base + ((size_t)gis[pi] * L_ + gjs[pj]) * CH);
            #pragma unroll
            for (int k = 0; k < 8; k++) {
                float4 o;
                if (valid) {
                    float2 lo = unpk(acc[p][2*k]);
                    float2 hi = unpk(acc[p][2*k+1]);
                    float4 bias = __ldg(b4 + k);
                    o.x = fmaxf(lo.x + bias.x, 0.f);
                    o.y = fmaxf(lo.y + bias.y, 0.f);
                    o.z = fmaxf(hi.x + bias.z, 0.f);
                    o.w = fmaxf(hi.y + bias.w, 0.f);
                } else {
                    o = make_float4(0.f, 0.f, 0.f, 0.f);
                }
                op[k] = o;
            }
        }
    }
}

// ============================================================
// Stage 2: 7x7x32->1 SAME conv + mask.
// 32x32 output tile, 256 threads, 1x4 outputs/thread, sliding window.
// Channels chunked by 4 in SMEM (30 KB total) -> high occupancy.
// ============================================================
#define SH_W2 40                   // padded col stride (float4-aligned)
#define SH_PL (38 * SH_W2)         // one channel plane: 38 rows

__global__ __launch_bounds__(256, 4)
void stage2_kernel(const int* __restrict__ plen_g, const float* __restrict__ W2,
                   const float* __restrict__ b2, float* __restrict__ out) {
    extern __shared__ float smem[];
    float* sw = smem;              // 1568 weights (pad to 1600)
    float* sh = smem + 1600;       // 4 channel planes

    const int b  = blockIdx.z;
    const int i0 = blockIdx.y * 32;
    const int j0 = blockIdx.x * 32;
    const int tid = threadIdx.x;
    const int row = tid >> 3;              // 0..31
    const int jc  = (tid & 7) * 4;         // 0,4,...,28
    const int plen = plen_g[b];
    const int i = i0 + row;

    float4* outp = reinterpret_cast<float4*>(
        out + ((size_t)(b * L_ + i) * L_ + j0 + jc));

    if (i0 >= plen || j0 >= plen) {        // fully masked tile
        *outp = make_float4(0.f, 0.f, 0.f, 0.f);
        return;
    }

    for (int idx = tid; idx < 1568; idx += 256) sw[idx] = W2[idx];

    float acc[4] = {0.f, 0.f, 0.f, 0.f};

    for (int cb = 0; cb < 8; cb++) {
        const int cbase = cb * 4;
        __syncthreads();   // sw ready (cb=0) / previous chunk's compute done
        // fill 38x38 halo tile, 4 channels per pixel (one float4)
        for (int p = tid; p < 38 * 38; p += 256) {
            int rr = p / 38, cc = p - rr * 38;
            int rg = i0 - 3 + rr, cg = j0 - 3 + cc;
            float4 v = make_float4(0.f, 0.f, 0.f, 0.f);
            if (rg >= 0 && rg < L_ && cg >= 0 && cg < L_) {
                v = *reinterpret_cast<const float4*>(
                    g_h + ((size_t)(b * L_ + rg) * L_ + cg) * CH + cbase);
            }
            float* d0 = sh + rr * SH_W2 + cc;
            d0[0 * SH_PL] = v.x; d0[1 * SH_PL] = v.y;
            d0[2 * SH_PL] = v.z; d0[3 * SH_PL] = v.w;
        }
        __syncthreads();

        #pragma unroll
        for (int ch = 0; ch < 4; ch++) {
            #pragma unroll
            for (int di = 0; di < 7; di++) {
                const float4* hp = reinterpret_cast<const float4*>(
                    sh + ch * SH_PL + (row + di) * SH_W2 + jc);
                float4 h0 = hp[0], h1 = hp[1], h2 = hp[2];
                float hr[12] = {h0.x, h0.y, h0.z, h0.w,
                                h1.x, h1.y, h1.z, h1.w,
                                h2.x, h2.y, h2.z, h2.w};
                const float* wr = sw + di * 7 * 32 + cbase + ch;
                #pragma unroll
                for (int dj = 0; dj < 7; dj++) {
                    float w = wr[dj * 32];     // warp-uniform broadcast
                    #pragma unroll
                    for (int q = 0; q < 4; q++)
                        acc[q] = fmaf(hr[q + dj], w, acc[q]);
                }
            }
        }
    }

    const float bias = b2[0];
    float4 o;
    {
        int j = j0 + jc;
        o.x = (i < plen && (j + 0) < plen) ? (acc[0] + bias) : 0.f;
        o.y = (i < plen && (j + 1) < plen) ? (acc[1] + bias) : 0.f;
        o.z = (i < plen && (j + 2) < plen) ? (acc[2] + bias) : 0.f;
        o.w = (i < plen && (j + 3) < plen) ? (acc[3] + bias) : 0.f;
    }
    *outp = o;
}

// ============================================================
extern "C" void kernel_launch(void* const* d_in, const int* in_sizes, int n_in,
                              void* d_out, int out_size) {
    const float* x  = (const float*)d_in[0];   // [8,256,256] f32
    const int*   pl = (const int*)  d_in[1];   // [8] i32
    const float* W1 = (const float*)d_in[2];   // [512,32] f32
    const float* b1 = (const float*)d_in[3];   // [32] f32
    const float* W2 = (const float*)d_in[4];   // [7,7,32,1] f32
    const float* b2 = (const float*)d_in[5];   // [1] f32
    float* out = (float*)d_out;                // [8,256,256,1] f32

    const int smem1 = (8192 + 48 * 257) * 4;          // 82112 B
    const int smem2 = (1600 + 4 * SH_PL) * 4;         // 30720 B
    cudaFuncSetAttribute(stage1_kernel, cudaFuncAttributeMaxDynamicSharedMemorySize, smem1);
    cudaFuncSetAttribute(stage2_kernel, cudaFuncAttributeMaxDynamicSharedMemorySize, smem2);

    dim3 g1(8, 16, 8);    // j-tiles, i-tiles, batch
    stage1_kernel<<<g1, 128, smem1>>>(x, pl, W1, b1);
    dim3 g2(8, 8, 8);
    stage2_kernel<<<g2, 256, smem2>>>(pl, W2, b2, out);
}

// round 10
// speedup vs baseline: 1.2043x; 1.0771x over previous
#include <cuda_runtime.h>
#include <cstdint>

#define B_ 8
#define L_ 256
#define D_ 256
#define CH 32

// 64 MB scratch for h = relu(z @ W1 + b1) * mask   [B][L][L][CH]
__device__ float g_h[(size_t)B_ * L_ * L_ * CH];

// ---------- packed f32x2 helpers (sm_103a) ----------
__device__ __forceinline__ unsigned long long ffma2(unsigned long long a,
                                                    unsigned long long b,
                                                    unsigned long long c) {
    unsigned long long d;
    asm("fma.rn.f32x2 %0, %1, %2, %3;" : "=l"(d) : "l"(a), "l"(b), "l"(c));
    return d;
}
__device__ __forceinline__ unsigned long long dup2(float x) {
    unsigned long long d;
    asm("mov.b64 %0, {%1, %1};" : "=l"(d) : "f"(x));
    return d;
}
__device__ __forceinline__ float2 unpk(unsigned long long v) {
    float2 r;
    asm("mov.b64 {%0, %1}, %2;" : "=f"(r.x), "=f"(r.y) : "l"(v));
    return r;
}

// ============================================================
// Stage 1: h[b,i,j,c] = relu( sum_d x[b,i,d]x[b,j,d] W1[d,c]
//                           + sum_d |x[b,i,d]-x[b,j,d]| W1[256+d,c] + b1[c] ) * m
// 16(i) x 32(j) tile, 128 threads, each thread 4 pairs (2i x 2j),
// 32 channels packed as 16 f32x2 per pair -> 64 u64 accumulators.
// W1 staged in 2 K-halves (32 KB each) so 2 CTAs/SM fit.  (unchanged from R7)
// ============================================================
__global__ __launch_bounds__(128, 2)
void stage1_kernel(const float* __restrict__ x, const int* __restrict__ plen_g,
                   const float* __restrict__ W1, const float* __restrict__ b1) {
    extern __shared__ float smem[];
    float* sWm = smem;                 // 128 x 32 (mul weights, current half)
    float* sWs = smem + 4096;          // 128 x 32 (sub weights, current half)
    float* sxi = smem + 8192;          // 16 rows * 257
    float* sxj = sxi + 16 * 257;       // 32 rows * 257

    const int b  = blockIdx.z;
    const int i0 = blockIdx.y * 16;
    const int j0 = blockIdx.x * 32;
    const int tid = threadIdx.x;
    const int ti = tid >> 4;           // 0..7
    const int tj = tid & 15;           // 0..15
    const int plen = plen_g[b];

    const int gi0 = i0 + ti, gi1 = i0 + ti + 8;
    const int gj0 = j0 + tj, gj1 = j0 + tj + 16;

    float* h_base = g_h + (size_t)b * L_ * L_ * CH;
    const int gis[2] = {gi0, gi1};
    const int gjs[2] = {gj0, gj1};

    if (i0 >= plen || j0 >= plen) {    // fully masked tile: zero-fill, bail
        float4 z = make_float4(0.f, 0.f, 0.f, 0.f);
        #pragma unroll
        for (int pi = 0; pi < 2; pi++)
            #pragma unroll
            for (int pj = 0; pj < 2; pj++) {
                float4* op = reinterpret_cast<float4*>(
                    h_base + ((size_t)gis[pi] * L_ + gjs[pj]) * CH);
                #pragma unroll
                for (int k = 0; k < 8; k++) op[k] = z;
            }
        return;
    }

    // stage x tiles (float4 global loads, scalar smem stores; stride 257)
    {
        const float* xb = x + (size_t)b * L_ * D_;
        const float4* xb4 = reinterpret_cast<const float4*>(xb);
        #pragma unroll
        for (int it = 0; it < 8; it++) {           // 16*64 float4
            int idx = tid + it * 128;
            int r = idx >> 6, c = (idx & 63) * 4;
            float4 v = xb4[(i0 + r) * 64 + (c >> 2)];
            float* d0 = sxi + r * 257 + c;
            d0[0] = v.x; d0[1] = v.y; d0[2] = v.z; d0[3] = v.w;
        }
        #pragma unroll
        for (int it = 0; it < 16; it++) {          // 32*64 float4
            int idx = tid + it * 128;
            int r = idx >> 6, c = (idx & 63) * 4;
            float4 v = xb4[(j0 + r) * 64 + (c >> 2)];
            float* d0 = sxj + r * 257 + c;
            d0[0] = v.x; d0[1] = v.y; d0[2] = v.z; d0[3] = v.w;
        }
    }

    unsigned long long acc[4][16];
    #pragma unroll
    for (int p = 0; p < 4; p++)
        #pragma unroll
        for (int k = 0; k < 16; k++) acc[p][k] = 0ULL;

    const float* xi0 = sxi + ti * 257;
    const float* xi1 = sxi + (ti + 8) * 257;
    const float* xj0 = sxj + tj * 257;
    const float* xj1 = sxj + (tj + 16) * 257;

    for (int half = 0; half < 2; half++) {
        if (half) __syncthreads();     // everyone done reading previous sW
        {
            const float4* wm4 = reinterpret_cast<const float4*>(W1 + half * 128 * 32);
            const float4* ws4 = reinterpret_cast<const float4*>(W1 + (256 + half * 128) * 32);
            float4* sm4 = reinterpret_cast<float4*>(sWm);
            float4* ss4 = reinterpret_cast<float4*>(sWs);
            #pragma unroll
            for (int k = 0; k < 8; k++) {
                sm4[tid + k * 128] = wm4[tid + k * 128];
                ss4[tid + k * 128] = ws4[tid + k * 128];
            }
        }
        __syncthreads();               // sW ready (and x tiles ready on half 0)

        const int dof = half * 128;
        #pragma unroll 2
        for (int dd = 0; dd < 128; dd++) {
            float a0 = xi0[dof + dd], a1 = xi1[dof + dd];
            float c0 = xj0[dof + dd], c1 = xj1[dof + dd];
            unsigned long long p00 = dup2(a0 * c0);
            unsigned long long p01 = dup2(a0 * c1);
            unsigned long long p10 = dup2(a1 * c0);
            unsigned long long p11 = dup2(a1 * c1);
            unsigned long long s00 = dup2(fabsf(a0 - c0));
            unsigned long long s01 = dup2(fabsf(a0 - c1));
            unsigned long long s10 = dup2(fabsf(a1 - c0));
            unsigned long long s11 = dup2(fabsf(a1 - c1));
            const ulonglong2* wm = reinterpret_cast<const ulonglong2*>(sWm + dd * 32);
            const ulonglong2* ws = reinterpret_cast<const ulonglong2*>(sWs + dd * 32);
            #pragma unroll
            for (int k = 0; k < 8; k++) {
                ulonglong2 M = wm[k];      // LDS.128, warp-uniform broadcast
                ulonglong2 S = ws[k];
                acc[0][2*k]   = ffma2(p00, M.x, acc[0][2*k]);
                acc[0][2*k+1] = ffma2(p00, M.y, acc[0][2*k+1]);
                acc[1][2*k]   = ffma2(p01, M.x, acc[1][2*k]);
                acc[1][2*k+1] = ffma2(p01, M.y, acc[1][2*k+1]);
                acc[2][2*k]   = ffma2(p10, M.x, acc[2][2*k]);
                acc[2][2*k+1] = ffma2(p10, M.y, acc[2][2*k+1]);
                acc[3][2*k]   = ffma2(p11, M.x, acc[3][2*k]);
                acc[3][2*k+1] = ffma2(p11, M.y, acc[3][2*k+1]);
                acc[0][2*k]   = ffma2(s00, S.x, acc[0][2*k]);
                acc[0][2*k+1] = ffma2(s00, S.y, acc[0][2*k+1]);
                acc[1][2*k]   = ffma2(s01, S.x, acc[1][2*k]);
                acc[1][2*k+1] = ffma2(s01, S.y, acc[1][2*k+1]);
                acc[2][2*k]   = ffma2(s10, S.x, acc[2][2*k]);
                acc[2][2*k+1] = ffma2(s10, S.y, acc[2][2*k+1]);
                acc[3][2*k]   = ffma2(s11, S.x, acc[3][2*k]);
                acc[3][2*k+1] = ffma2(s11, S.y, acc[3][2*k+1]);
            }
        }
    }

    // epilogue: bias + relu + mask, 4 pairs
    const float4* b4 = reinterpret_cast<const float4*>(b1);
    #pragma unroll
    for (int pi = 0; pi < 2; pi++) {
        #pragma unroll
        for (int pj = 0; pj < 2; pj++) {
            const int p = pi * 2 + pj;
            const bool valid = (gis[pi] < plen) && (gjs[pj] < plen);
            float4* op = reinterpret_cast<float4*>(
                h_base + ((size_t)gis[pi] * L_ + gjs[pj]) * CH);
            #pragma unroll
            for (int k = 0; k < 8; k++) {
                float4 o;
                if (valid) {
                    float2 lo = unpk(acc[p][2*k]);
                    float2 hi = unpk(acc[p][2*k+1]);
                    float4 bias = __ldg(b4 + k);
                    o.x = fmaxf(lo.x + bias.x, 0.f);
                    o.y = fmaxf(lo.y + bias.y, 0.f);
                    o.z = fmaxf(hi.x + bias.z, 0.f);
                    o.w = fmaxf(hi.y + bias.w, 0.f);
                } else {
                    o = make_float4(0.f, 0.f, 0.f, 0.f);
                }
                op[k] = o;
            }
        }
    }
}

// ============================================================
// Stage 2: 7x7x32->1 SAME conv + mask, f32x2 over CHANNEL PAIRS.
// 32x32 output tile, 256 threads, 1x4 outputs/thread.
// smem holds 4 channel-pair planes (= 8 channels) per chunk, 4 chunks.
// h pairs and W2 pairs are memory-contiguous -> LDS feeds FFMA2 directly,
// horizontal add once per output at the end.
// ============================================================
#define S2_W  40                   // u64 (channel-pair) stride per halo row
#define S2_PL (38 * S2_W)          // u64 elems per pair-plane

__global__ __launch_bounds__(256)
void stage2_kernel(const int* __restrict__ plen_g, const float* __restrict__ W2,
                   const float* __restrict__ b2, float* __restrict__ out) {
    extern __shared__ float smem[];
    float*  swf = smem;                                   // W2 copy: 1568 floats = 784 u64 pairs
    float2* sh2 = reinterpret_cast<float2*>(smem + 1600); // 4 pair-planes

    const int b  = blockIdx.z;
    const int i0 = blockIdx.y * 32;
    const int j0 = blockIdx.x * 32;
    const int tid = threadIdx.x;
    const int row = tid >> 3;              // 0..31
    const int jq  = (tid & 7) * 4;         // 0,4,...,28
    const int plen = plen_g[b];
    const int i = i0 + row;

    float4* outp = reinterpret_cast<float4*>(
        out + ((size_t)(b * L_ + i) * L_ + j0 + jq));

    if (i0 >= plen || j0 >= plen) {        // fully masked tile
        *outp = make_float4(0.f, 0.f, 0.f, 0.f);
        return;
    }

    // stage W2 (contiguous channel pairs)
    {
        const float4* w4 = reinterpret_cast<const float4*>(W2);
        float4* s4 = reinterpret_cast<float4*>(swf);
        for (int idx = tid; idx < 392; idx += 256) s4[idx] = w4[idx];
    }
    const unsigned long long* swu = reinterpret_cast<const unsigned long long*>(swf);

    unsigned long long acc2[4] = {0ULL, 0ULL, 0ULL, 0ULL};

    for (int chunk = 0; chunk < 4; chunk++) {
        __syncthreads();   // weights staged (chunk 0) / prev chunk's compute done
        // fill 38x38 halo: 8 channels per pixel -> 4 pair-planes
        for (int p = tid; p < 38 * 38; p += 256) {
            int rr = p / 38, cc = p - rr * 38;
            int rg = i0 - 3 + rr, cg = j0 - 3 + cc;
            float4 v0 = make_float4(0.f, 0.f, 0.f, 0.f);
            float4 v1 = v0;
            if ((unsigned)rg < L_ && (unsigned)cg < L_) {
                const float4* hp = reinterpret_cast<const float4*>(
                    g_h + ((size_t)(b * L_ + rg) * L_ + cg) * CH + chunk * 8);
                v0 = hp[0];
                v1 = hp[1];
            }
            float2* d0 = sh2 + rr * S2_W + cc;
            d0[0 * S2_PL] = make_float2(v0.x, v0.y);
            d0[1 * S2_PL] = make_float2(v0.z, v0.w);
            d0[2 * S2_PL] = make_float2(v1.x, v1.y);
            d0[3 * S2_PL] = make_float2(v1.z, v1.w);
        }
        __syncthreads();

        #pragma unroll
        for (int cp = 0; cp < 4; cp++) {
            const int gcp = chunk * 4 + cp;        // global channel-pair 0..15
            #pragma unroll
            for (int di = 0; di < 7; di++) {
                // 10-wide u64 sliding window: pixels jq..jq+9 of halo row (row+di)
                const ulonglong2* wr = reinterpret_cast<const ulonglong2*>(
                    sh2 + cp * S2_PL + (row + di) * S2_W + jq);
                ulonglong2 a0 = wr[0], a1 = wr[1], a2 = wr[2], a3 = wr[3], a4 = wr[4];
                unsigned long long win[10] = {a0.x, a0.y, a1.x, a1.y, a2.x,
                                              a2.y, a3.x, a3.y, a4.x, a4.y};
                #pragma unroll
                for (int dj = 0; dj < 7; dj++) {
                    unsigned long long wp = swu[(di * 7 + dj) * 16 + gcp]; // uniform LDS.64
                    acc2[0] = ffma2(win[dj],     wp, acc2[0]);
                    acc2[1] = ffma2(win[dj + 1], wp, acc2[1]);
                    acc2[2] = ffma2(win[dj + 2], wp, acc2[2]);
                    acc2[3] = ffma2(win[dj + 3], wp, acc2[3]);
                }
            }
        }
    }

    const float bias = b2[0];
    float4 o;
    {
        int j = j0 + jq;
        float2 r0 = unpk(acc2[0]);
        float2 r1 = unpk(acc2[1]);
        float2 r2 = unpk(acc2[2]);
        float2 r3 = unpk(acc2[3]);
        o.x = (i < plen && (j + 0) < plen) ? (r0.x + r0.y + bias) : 0.f;
        o.y = (i < plen && (j + 1) < plen) ? (r1.x + r1.y + bias) : 0.f;
        o.z = (i < plen && (j + 2) < plen) ? (r2.x + r2.y + bias) : 0.f;
        o.w = (i < plen && (j + 3) < plen) ? (r3.x + r3.y + bias) : 0.f;
    }
    *outp = o;
}

// ============================================================
extern "C" void kernel_launch(void* const* d_in, const int* in_sizes, int n_in,
                              void* d_out, int out_size) {
    const float* x  = (const float*)d_in[0];   // [8,256,256] f32
    const int*   pl = (const int*)  d_in[1];   // [8] i32
    const float* W1 = (const float*)d_in[2];   // [512,32] f32
    const float* b1 = (const float*)d_in[3];   // [32] f32
    const float* W2 = (const float*)d_in[4];   // [7,7,32,1] f32
    const float* b2 = (const float*)d_in[5];   // [1] f32
    float* out = (float*)d_out;                // [8,256,256,1] f32

    const int smem1 = (8192 + 48 * 257) * 4;             // 82112 B
    const int smem2 = 1600 * 4 + 4 * S2_PL * 8;          // 6400 + 48640 = 55040 B
    cudaFuncSetAttribute(stage1_kernel, cudaFuncAttributeMaxDynamicSharedMemorySize, smem1);
    cudaFuncSetAttribute(stage2_kernel, cudaFuncAttributeMaxDynamicSharedMemorySize, smem2);

    dim3 g1(8, 16, 8);    // j-tiles, i-tiles, batch
    stage1_kernel<<<g1, 128, smem1>>>(x, pl, W1, b1);
    dim3 g2(8, 8, 8);
    stage2_kernel<<<g2, 256, smem2>>>(pl, W2, b2, out);
}

// round 15
// speedup vs baseline: 1.6471x; 1.3677x over previous
#include <cuda_runtime.h>
#include <cstdint>

#define B_ 8
#define L_ 256
#define D_ 256
#define CH 32

// 64 MB scratch for h = relu(z @ W1 + b1) * mask   [B][L][L][CH]
__device__ float g_h[(size_t)B_ * L_ * L_ * CH];

// ---------- packed f32x2 helpers (sm_103a) ----------
__device__ __forceinline__ unsigned long long ffma2(unsigned long long a,
                                                    unsigned long long b,
                                                    unsigned long long c) {
    unsigned long long d;
    asm("fma.rn.f32x2 %0, %1, %2, %3;" : "=l"(d) : "l"(a), "l"(b), "l"(c));
    return d;
}
__device__ __forceinline__ unsigned long long dup2(float x) {
    unsigned long long d;
    asm("mov.b64 %0, {%1, %1};" : "=l"(d) : "f"(x));
    return d;
}
__device__ __forceinline__ float2 unpk(unsigned long long v) {
    float2 r;
    asm("mov.b64 {%0, %1}, %2;" : "=f"(r.x), "=f"(r.y) : "l"(v));
    return r;
}

// ============================================================
// Stage 1 with SYMMETRY: h[b,i,j,:] == h[b,j,i,:] (mul, |sub|, mask all
// symmetric). 16(i) x 32(j) tiles:
//   strictly-lower (i0 >= j0+32): exit, covered by an upper tile's mirror
//   strictly-upper (i0+16 <= j0): compute, store own + transposed mirror
//   diagonal-straddling:          compute, store own only
// 128 threads, 4 pairs/thread (2i x 2j), 16 f32x2 accumulators per pair.
// ============================================================
__global__ __launch_bounds__(128, 2)
void stage1_kernel(const float* __restrict__ x, const int* __restrict__ plen_g,
                   const float* __restrict__ W1, const float* __restrict__ b1) {
    extern __shared__ float smem[];
    float* sWm = smem;                 // 128 x 32 (mul weights, current half)
    float* sWs = smem + 4096;          // 128 x 32 (sub weights, current half)
    float* sxi = smem + 8192;          // 16 rows * 257
    float* sxj = sxi + 16 * 257;       // 32 rows * 257

    const int i0 = blockIdx.y * 16;
    const int j0 = blockIdx.x * 32;

    if (i0 >= j0 + 32) return;                 // strictly-lower: mirrored by partner
    const bool upper = (i0 + 16 <= j0);        // store mirror too

    const int b  = blockIdx.z;
    const int tid = threadIdx.x;
    const int ti = tid >> 4;           // 0..7
    const int tj = tid & 15;           // 0..15
    const int plen = plen_g[b];

    const int gis[2] = {i0 + ti, i0 + ti + 8};
    const int gjs[2] = {j0 + tj, j0 + tj + 16};

    float* h_base = g_h + (size_t)b * L_ * L_ * CH;

    if (i0 >= plen || j0 >= plen) {    // fully masked: zero own (+mirror), bail
        float4 z = make_float4(0.f, 0.f, 0.f, 0.f);
        #pragma unroll
        for (int pi = 0; pi < 2; pi++)
            #pragma unroll
            for (int pj = 0; pj < 2; pj++) {
                float4* op = reinterpret_cast<float4*>(
                    h_base + ((size_t)gis[pi] * L_ + gjs[pj]) * CH);
                #pragma unroll
                for (int k = 0; k < 8; k++) op[k] = z;
                if (upper) {
                    float4* om = reinterpret_cast<float4*>(
                        h_base + ((size_t)gjs[pj] * L_ + gis[pi]) * CH);
                    #pragma unroll
                    for (int k = 0; k < 8; k++) om[k] = z;
                }
            }
        return;
    }

    // stage x tiles (float4 global loads, scalar smem stores; stride 257)
    {
        const float* xb = x + (size_t)b * L_ * D_;
        const float4* xb4 = reinterpret_cast<const float4*>(xb);
        #pragma unroll
        for (int it = 0; it < 8; it++) {           // 16*64 float4
            int idx = tid + it * 128;
            int r = idx >> 6, c = (idx & 63) * 4;
            float4 v = xb4[(i0 + r) * 64 + (c >> 2)];
            float* d0 = sxi + r * 257 + c;
            d0[0] = v.x; d0[1] = v.y; d0[2] = v.z; d0[3] = v.w;
        }
        #pragma unroll
        for (int it = 0; it < 16; it++) {          // 32*64 float4
            int idx = tid + it * 128;
            int r = idx >> 6, c = (idx & 63) * 4;
            float4 v = xb4[(j0 + r) * 64 + (c >> 2)];
            float* d0 = sxj + r * 257 + c;
            d0[0] = v.x; d0[1] = v.y; d0[2] = v.z; d0[3] = v.w;
        }
    }

    unsigned long long acc[4][16];
    #pragma unroll
    for (int p = 0; p < 4; p++)
        #pragma unroll
        for (int k = 0; k < 16; k++) acc[p][k] = 0ULL;

    const float* xi0 = sxi + ti * 257;
    const float* xi1 = sxi + (ti + 8) * 257;
    const float* xj0 = sxj + tj * 257;
    const float* xj1 = sxj + (tj + 16) * 257;

    for (int half = 0; half < 2; half++) {
        if (half) __syncthreads();
        {
            const float4* wm4 = reinterpret_cast<const float4*>(W1 + half * 128 * 32);
            const float4* ws4 = reinterpret_cast<const float4*>(W1 + (256 + half * 128) * 32);
            float4* sm4 = reinterpret_cast<float4*>(sWm);
            float4* ss4 = reinterpret_cast<float4*>(sWs);
            #pragma unroll
            for (int k = 0; k < 8; k++) {
                sm4[tid + k * 128] = wm4[tid + k * 128];
                ss4[tid + k * 128] = ws4[tid + k * 128];
            }
        }
        __syncthreads();

        const int dof = half * 128;
        #pragma unroll 2
        for (int dd = 0; dd < 128; dd++) {
            float a0 = xi0[dof + dd], a1 = xi1[dof + dd];
            float c0 = xj0[dof + dd], c1 = xj1[dof + dd];
            unsigned long long p00 = dup2(a0 * c0);
            unsigned long long p01 = dup2(a0 * c1);
            unsigned long long p10 = dup2(a1 * c0);
            unsigned long long p11 = dup2(a1 * c1);
            unsigned long long s00 = dup2(fabsf(a0 - c0));
            unsigned long long s01 = dup2(fabsf(a0 - c1));
            unsigned long long s10 = dup2(fabsf(a1 - c0));
            unsigned long long s11 = dup2(fabsf(a1 - c1));
            const ulonglong2* wm = reinterpret_cast<const ulonglong2*>(sWm + dd * 32);
            const ulonglong2* ws = reinterpret_cast<const ulonglong2*>(sWs + dd * 32);
            #pragma unroll
            for (int k = 0; k < 8; k++) {
                ulonglong2 M = wm[k];      // LDS.128, warp-uniform broadcast
                ulonglong2 S = ws[k];
                acc[0][2*k]   = ffma2(p00, M.x, acc[0][2*k]);
                acc[0][2*k+1] = ffma2(p00, M.y, acc[0][2*k+1]);
                acc[1][2*k]   = ffma2(p01, M.x, acc[1][2*k]);
                acc[1][2*k+1] = ffma2(p01, M.y, acc[1][2*k+1]);
                acc[2][2*k]   = ffma2(p10, M.x, acc[2][2*k]);
                acc[2][2*k+1] = ffma2(p10, M.y, acc[2][2*k+1]);
                acc[3][2*k]   = ffma2(p11, M.x, acc[3][2*k]);
                acc[3][2*k+1] = ffma2(p11, M.y, acc[3][2*k+1]);
                acc[0][2*k]   = ffma2(s00, S.x, acc[0][2*k]);
                acc[0][2*k+1] = ffma2(s00, S.y, acc[0][2*k+1]);
                acc[1][2*k]   = ffma2(s01, S.x, acc[1][2*k]);
                acc[1][2*k+1] = ffma2(s01, S.y, acc[1][2*k+1]);
                acc[2][2*k]   = ffma2(s10, S.x, acc[2][2*k]);
                acc[2][2*k+1] = ffma2(s10, S.y, acc[2][2*k+1]);
                acc[3][2*k]   = ffma2(s11, S.x, acc[3][2*k]);
                acc[3][2*k+1] = ffma2(s11, S.y, acc[3][2*k+1]);
            }
        }
    }

    // epilogue: bias + relu + mask; own store, plus mirror store if upper
    const float4* b4 = reinterpret_cast<const float4*>(b1);
    #pragma unroll
    for (int pi = 0; pi < 2; pi++) {
        #pragma unroll
        for (int pj = 0; pj < 2; pj++) {
            const int p = pi * 2 + pj;
            const bool valid = (gis[pi] < plen) && (gjs[pj] < plen);
            float4 o[8];
            #pragma unroll
            for (int k = 0; k < 8; k++) {
                if (valid) {
                    float2 lo = unpk(acc[p][2*k]);
                    float2 hi = unpk(acc[p][2*k+1]);
                    float4 bias = __ldg(b4 + k);
                    o[k].x = fmaxf(lo.x + bias.x, 0.f);
                    o[k].y = fmaxf(lo.y + bias.y, 0.f);
                    o[k].z = fmaxf(hi.x + bias.z, 0.f);
                    o[k].w = fmaxf(hi.y + bias.w, 0.f);
                } else {
                    o[k] = make_float4(0.f, 0.f, 0.f, 0.f);
                }
            }
            float4* op = reinterpret_cast<float4*>(
                h_base + ((size_t)gis[pi] * L_ + gjs[pj]) * CH);
            #pragma unroll
            for (int k = 0; k < 8; k++) op[k] = o[k];
            if (upper) {
                float4* om = reinterpret_cast<float4*>(
                    h_base + ((size_t)gjs[pj] * L_ + gis[pi]) * CH);
                #pragma unroll
                for (int k = 0; k < 8; k++) om[k] = o[k];
            }
        }
    }
}

// ============================================================
// Stage 2: 7x7x32->1 SAME conv + mask, f32x2 over channel pairs.
// 32x32 tile, 128 threads, 8 outputs/thread (Q=8): 7 LDS.128 per window
// feed 56 FFMA2. Plane stride 42 u64 -> max 2-way bank conflicts.
// 8-channel chunks (4 pair-planes), 4 chunks. ~57.5 KB smem, 3 CTAs/SM.
// ============================================================
#define S2_W  42                   // u64 stride per halo row (even, mod16=10)
#define S2_PL (38 * S2_W)          // u64 elems per pair-plane (1596)

__global__ __launch_bounds__(128)
void stage2_kernel(const int* __restrict__ plen_g, const float* __restrict__ W2,
                   const float* __restrict__ b2, float* __restrict__ out) {
    extern __shared__ float smem[];
    float*  swf = smem;                                   // W2: 1568 floats (pad 1600)
    float2* sh2 = reinterpret_cast<float2*>(smem + 1600); // 4 pair-planes

    const int b  = blockIdx.z;
    const int i0 = blockIdx.y * 32;
    const int j0 = blockIdx.x * 32;
    const int tid = threadIdx.x;
    const int row = tid >> 2;              // 0..31
    const int jq  = (tid & 3) * 8;         // 0,8,16,24
    const int plen = plen_g[b];
    const int i = i0 + row;

    float4* outp = reinterpret_cast<float4*>(
        out + ((size_t)(b * L_ + i) * L_ + j0 + jq));

    if (i0 >= plen || j0 >= plen) {        // fully masked tile
        float4 z = make_float4(0.f, 0.f, 0.f, 0.f);
        outp[0] = z; outp[1] = z;
        return;
    }

    // stage W2 (contiguous channel pairs)
    {
        const float4* w4 = reinterpret_cast<const float4*>(W2);
        float4* s4 = reinterpret_cast<float4*>(swf);
        for (int idx = tid; idx < 392; idx += 128) s4[idx] = w4[idx];
    }
    const unsigned long long* swu = reinterpret_cast<const unsigned long long*>(swf);

    unsigned long long acc2[8];
    #pragma unroll
    for (int q = 0; q < 8; q++) acc2[q] = 0ULL;

    #pragma unroll 1
    for (int chunk = 0; chunk < 4; chunk++) {
        __syncthreads();   // weights staged (chunk 0) / prev chunk compute done
        // fill 38x38 halo: 8 channels per pixel -> 4 pair-planes
        for (int p = tid; p < 38 * 38; p += 128) {
            int rr = p / 38, cc = p - rr * 38;
            int rg = i0 - 3 + rr, cg = j0 - 3 + cc;
            float4 v0 = make_float4(0.f, 0.f, 0.f, 0.f);
            float4 v1 = v0;
            if ((unsigned)rg < L_ && (unsigned)cg < L_) {
                const float4* hp = reinterpret_cast<const float4*>(
                    g_h + ((size_t)(b * L_ + rg) * L_ + cg) * CH + chunk * 8);
                v0 = hp[0];
                v1 = hp[1];
            }
            float2* d0 = sh2 + rr * S2_W + cc;
            d0[0 * S2_PL] = make_float2(v0.x, v0.y);
            d0[1 * S2_PL] = make_float2(v0.z, v0.w);
            d0[2 * S2_PL] = make_float2(v1.x, v1.y);
            d0[3 * S2_PL] = make_float2(v1.z, v1.w);
        }
        __syncthreads();

        #pragma unroll
        for (int cp = 0; cp < 4; cp++) {
            const int gcp = chunk * 4 + cp;        // global channel-pair 0..15
            #pragma unroll
            for (int di = 0; di < 7; di++) {
                // 14-wide u64 sliding window: pixels jq..jq+13 (aligned: jq even)
                const ulonglong2* wr = reinterpret_cast<const ulonglong2*>(
                    sh2 + cp * S2_PL + (row + di) * S2_W + jq);
                ulonglong2 a0 = wr[0], a1 = wr[1], a2 = wr[2], a3 = wr[3],
                           a4 = wr[4], a5 = wr[5], a6 = wr[6];
                unsigned long long win[14] = {a0.x, a0.y, a1.x, a1.y, a2.x, a2.y,
                                              a3.x, a3.y, a4.x, a4.y, a5.x, a5.y,
                                              a6.x, a6.y};
                #pragma unroll
                for (int dj = 0; dj < 7; dj++) {
                    unsigned long long wp = swu[(di * 7 + dj) * 16 + gcp]; // uniform
                    #pragma unroll
                    for (int q = 0; q < 8; q++)
                        acc2[q] = ffma2(win[dj + q], wp, acc2[q]);
                }
            }
        }
    }

    const float bias = b2[0];
    float res[8];
    #pragma unroll
    for (int q = 0; q < 8; q++) {
        float2 r = unpk(acc2[q]);
        int j = j0 + jq + q;
        res[q] = (i < plen && j < plen) ? (r.x + r.y + bias) : 0.f;
    }
    outp[0] = make_float4(res[0], res[1], res[2], res[3]);
    outp[1] = make_float4(res[4], res[5], res[6], res[7]);
}

// ============================================================
extern "C" void kernel_launch(void* const* d_in, const int* in_sizes, int n_in,
                              void* d_out, int out_size) {
    const float* x  = (const float*)d_in[0];   // [8,256,256] f32
    const int*   pl = (const int*)  d_in[1];   // [8] i32
    const float* W1 = (const float*)d_in[2];   // [512,32] f32
    const float* b1 = (const float*)d_in[3];   // [32] f32
    const float* W2 = (const float*)d_in[4];   // [7,7,32,1] f32
    const float* b2 = (const float*)d_in[5];   // [1] f32
    float* out = (float*)d_out;                // [8,256,256,1] f32

    const int smem1 = (8192 + 48 * 257) * 4;             // 82112 B
    const int smem2 = 1600 * 4 + 4 * S2_PL * 8;          // 6400 + 51072 = 57472 B
    cudaFuncSetAttribute(stage1_kernel, cudaFuncAttributeMaxDynamicSharedMemorySize, smem1);
    cudaFuncSetAttribute(stage2_kernel, cudaFuncAttributeMaxDynamicSharedMemorySize, smem2);

    dim3 g1(8, 16, 8);    // j-tiles, i-tiles, batch
    stage1_kernel<<<g1, 128, smem1>>>(x, pl, W1, b1);
    dim3 g2(8, 8, 8);
    stage2_kernel<<<g2, 128, smem2>>>(pl, W2, b2, out);
}